// round 3
// baseline (speedup 1.0000x reference)
#include <cuda_runtime.h>

#define NN      100000
#define EE      1600000
#define INC     165
#define C1      128
#define C2      64

// ---------------- scratch (static device globals; no runtime alloc) ----------------
__device__ int   g_cnt[NN];
__device__ int   g_cur[NN];
__device__ int   g_incl[NN];
__device__ int   g_rowptr[NN + 1];
__device__ int   g_bsum[128];
__device__ float g_dinv[NN];
__device__ int   g_col[EE];
__device__ float g_H1[(size_t)NN * C1];
__device__ float g_A1[(size_t)NN * C1];
__device__ float g_H2[(size_t)NN * C2];
__device__ float g_A2[(size_t)NN * C2];

// ---------------- CSR build ----------------
__global__ void k_zero(int n) {
    int i = blockIdx.x * blockDim.x + threadIdx.x;
    if (i < n) { g_cnt[i] = 0; g_cur[i] = 0; }
}

__global__ void k_hist(const int* __restrict__ dst, int e) {
    int i = blockIdx.x * blockDim.x + threadIdx.x;
    if (i < e) atomicAdd(&g_cnt[dst[i]], 1);
}

// block scans 2048 elements (512 threads x 4)
__global__ void k_scan1(int n) {
    __shared__ int s[512];
    int tid  = threadIdx.x;
    int base = blockIdx.x * 2048 + tid * 4;
    int v[4];
    int local = 0;
#pragma unroll
    for (int i = 0; i < 4; i++) {
        int idx = base + i;
        int t = (idx < n) ? g_cnt[idx] : 0;
        v[i] = t; local += t;
    }
    s[tid] = local;
    __syncthreads();
    for (int off = 1; off < 512; off <<= 1) {
        int t = (tid >= off) ? s[tid - off] : 0;
        __syncthreads();
        s[tid] += t;
        __syncthreads();
    }
    int run = s[tid] - local;   // exclusive across threads
#pragma unroll
    for (int i = 0; i < 4; i++) {
        run += v[i];
        int idx = base + i;
        if (idx < n) g_incl[idx] = run;   // inclusive scan value
    }
    if (tid == 511) g_bsum[blockIdx.x] = s[511];
}

__global__ void k_scan2(int nb) {
    __shared__ int s[128];
    int tid = threadIdx.x;
    int v = (tid < nb) ? g_bsum[tid] : 0;
    s[tid] = v;
    __syncthreads();
    for (int off = 1; off < 128; off <<= 1) {
        int t = (tid >= off) ? s[tid - off] : 0;
        __syncthreads();
        s[tid] += t;
        __syncthreads();
    }
    g_bsum[tid] = s[tid] - v;   // exclusive block offsets
}

__global__ void k_finalize(int n, int e) {
    int i = blockIdx.x * blockDim.x + threadIdx.x;
    if (i < n) {
        g_rowptr[i] = g_incl[i] - g_cnt[i] + g_bsum[i >> 11];
        g_dinv[i]   = rsqrtf((float)g_cnt[i] + 1.0f);
    }
    if (i == 0) g_rowptr[n] = e;
}

__global__ void k_fill(const int* __restrict__ src, const int* __restrict__ dst, int e) {
    int i = blockIdx.x * blockDim.x + threadIdx.x;
    if (i < e) {
        int d = dst[i];
        int p = g_rowptr[d] + atomicAdd(&g_cur[d], 1);
        g_col[p] = src[i];
    }
}

// ---------------- GEMM1: H1 = X @ W1   (K=165, N=128), tile 64x128 ----------------
__global__ void k_gemm1(const float* __restrict__ X, const float* __restrict__ W, int n) {
    __shared__ float xs[64][33];     // K tile = 33 (165 = 5*33)
    __shared__ float ws[33][128];
    int tid = threadIdx.x;
    int c4  = (tid & 31) * 4;        // column (float4 group)
    int r0  = tid >> 5;              // base row 0..7
    int rowBase = blockIdx.x * 64;
    float4 acc[8];
#pragma unroll
    for (int j = 0; j < 8; j++) acc[j] = make_float4(0.f, 0.f, 0.f, 0.f);

    for (int kt = 0; kt < 5; kt++) {
        for (int i = tid; i < 64 * 33; i += 256) {
            int r = i / 33, c = i - r * 33;
            int gr = rowBase + r;
            xs[r][c] = (gr < n) ? X[(size_t)gr * INC + kt * 33 + c] : 0.f;
        }
        for (int i = tid; i < 33 * 128; i += 256) {
            int k = i >> 7, c = i & 127;
            ws[k][c] = W[(size_t)(kt * 33 + k) * C1 + c];
        }
        __syncthreads();
        for (int k = 0; k < 33; k++) {
            float4 wv = *(const float4*)&ws[k][c4];
#pragma unroll
            for (int j = 0; j < 8; j++) {
                float xv = xs[r0 + 8 * j][k];
                acc[j].x += xv * wv.x; acc[j].y += xv * wv.y;
                acc[j].z += xv * wv.z; acc[j].w += xv * wv.w;
            }
        }
        __syncthreads();
    }
#pragma unroll
    for (int j = 0; j < 8; j++) {
        int gr = rowBase + r0 + 8 * j;
        if (gr < n) *(float4*)&g_H1[(size_t)gr * C1 + c4] = acc[j];
    }
}

// ---------------- GEMM2: H2 = A1 @ W2   (K=128, N=64), tile 64x64 ----------------
__global__ void k_gemm2(const float* __restrict__ W, int n) {
    __shared__ float xs[64][33];     // K tile = 32 (pad to 33)
    __shared__ float ws[32][64];
    int tid = threadIdx.x;
    int c4  = (tid & 15) * 4;
    int r0  = tid >> 4;              // 0..15
    int rowBase = blockIdx.x * 64;
    float4 acc[4];
#pragma unroll
    for (int j = 0; j < 4; j++) acc[j] = make_float4(0.f, 0.f, 0.f, 0.f);

    for (int kt = 0; kt < 4; kt++) {
        for (int i = tid; i < 64 * 32; i += 256) {
            int r = i >> 5, c = i & 31;
            int gr = rowBase + r;
            xs[r][c] = (gr < n) ? g_A1[(size_t)gr * C1 + kt * 32 + c] : 0.f;
        }
        for (int i = tid; i < 32 * 64; i += 256) {
            int k = i >> 6, c = i & 63;
            ws[k][c] = W[(size_t)(kt * 32 + k) * C2 + c];
        }
        __syncthreads();
        for (int k = 0; k < 32; k++) {
            float4 wv = *(const float4*)&ws[k][c4];
#pragma unroll
            for (int j = 0; j < 4; j++) {
                float xv = xs[r0 + 16 * j][k];
                acc[j].x += xv * wv.x; acc[j].y += xv * wv.y;
                acc[j].z += xv * wv.z; acc[j].w += xv * wv.w;
            }
        }
        __syncthreads();
    }
#pragma unroll
    for (int j = 0; j < 4; j++) {
        int gr = rowBase + r0 + 16 * j;
        if (gr < n) *(float4*)&g_H2[(size_t)gr * C2 + c4] = acc[j];
    }
}

// ---------------- aggregation: warp per dst node, gather from CSR ----------------
__global__ void k_agg1(const float* __restrict__ b, int n) {
    int g    = blockIdx.x * blockDim.x + threadIdx.x;
    int node = g >> 5;
    int lane = g & 31;
    if (node >= n) return;
    float di = g_dinv[node];
    float sw = di * di;
    float4 acc = *((const float4*)(g_H1 + (size_t)node * C1) + lane);
    acc.x *= sw; acc.y *= sw; acc.z *= sw; acc.w *= sw;
    int beg = g_rowptr[node], end = g_rowptr[node + 1];
    for (int e = beg; e < end; e++) {
        int s    = g_col[e];
        float nw = di * g_dinv[s];
        float4 h = *((const float4*)(g_H1 + (size_t)s * C1) + lane);
        acc.x += nw * h.x; acc.y += nw * h.y;
        acc.z += nw * h.z; acc.w += nw * h.w;
    }
    float4 bb = *((const float4*)b + lane);
    float4 o;
    o.x = fmaxf(acc.x + bb.x, 0.f);
    o.y = fmaxf(acc.y + bb.y, 0.f);
    o.z = fmaxf(acc.z + bb.z, 0.f);
    o.w = fmaxf(acc.w + bb.w, 0.f);
    *((float4*)(g_A1 + (size_t)node * C1) + lane) = o;
}

__global__ void k_agg2(const float* __restrict__ b, int n) {
    int g    = blockIdx.x * blockDim.x + threadIdx.x;
    int node = g >> 5;
    int lane = g & 31;
    if (node >= n) return;
    float di = g_dinv[node];
    float sw = di * di;
    float2 acc = *((const float2*)(g_H2 + (size_t)node * C2) + lane);
    acc.x *= sw; acc.y *= sw;
    int beg = g_rowptr[node], end = g_rowptr[node + 1];
    for (int e = beg; e < end; e++) {
        int s    = g_col[e];
        float nw = di * g_dinv[s];
        float2 h = *((const float2*)(g_H2 + (size_t)s * C2) + lane);
        acc.x += nw * h.x; acc.y += nw * h.y;
    }
    float2 bb = *((const float2*)b + lane);
    float2 o;
    o.x = fmaxf(acc.x + bb.x, 0.f);
    o.y = fmaxf(acc.y + bb.y, 0.f);
    *((float2*)(g_A2 + (size_t)node * C2) + lane) = o;
}

// ---------------- final: out = A2 @ Wo + bo  (K=64, N=2) ----------------
__global__ void k_out(const float* __restrict__ Wo, const float* __restrict__ bo,
                      float* __restrict__ out, int n) {
    __shared__ float wo[128];
    int tid = threadIdx.x;
    if (tid < 128) wo[tid] = Wo[tid];
    __syncthreads();
    int i = blockIdx.x * blockDim.x + tid;
    if (i >= n) return;
    const float4* a = (const float4*)(g_A2 + (size_t)i * C2);
    float d0 = 0.f, d1 = 0.f;
#pragma unroll
    for (int q = 0; q < 16; q++) {
        float4 v = a[q];
        d0 += v.x * wo[(q * 4 + 0) * 2] + v.y * wo[(q * 4 + 1) * 2]
            + v.z * wo[(q * 4 + 2) * 2] + v.w * wo[(q * 4 + 3) * 2];
        d1 += v.x * wo[(q * 4 + 0) * 2 + 1] + v.y * wo[(q * 4 + 1) * 2 + 1]
            + v.z * wo[(q * 4 + 2) * 2 + 1] + v.w * wo[(q * 4 + 3) * 2 + 1];
    }
    float2 r;
    r.x = d0 + bo[0];
    r.y = d1 + bo[1];
    *((float2*)out + i) = r;
}

// ---------------- launch ----------------
extern "C" void kernel_launch(void* const* d_in, const int* in_sizes, int n_in,
                              void* d_out, int out_size) {
    const float* x   = (const float*)d_in[0];
    const int*   ei  = (const int*)  d_in[1];
    const float* W1  = (const float*)d_in[2];
    const float* b1  = (const float*)d_in[3];
    const float* W2  = (const float*)d_in[4];
    const float* b2  = (const float*)d_in[5];
    const float* Wo  = (const float*)d_in[6];
    const float* bo  = (const float*)d_in[7];

    int n = in_sizes[0] / INC;       // 100000
    int e = in_sizes[1] / 2;         // 1600000
    const int* src = ei;
    const int* dst = ei + e;

    int nb = (n + 2047) / 2048;

    k_zero    <<<(n + 255) / 256, 256>>>(n);
    k_hist    <<<(e + 255) / 256, 256>>>(dst, e);
    k_scan1   <<<nb, 512>>>(n);
    k_scan2   <<<1, 128>>>(nb);
    k_finalize<<<(n + 255) / 256, 256>>>(n, e);
    k_fill    <<<(e + 255) / 256, 256>>>(src, dst, e);

    k_gemm1   <<<(n + 63) / 64, 256>>>(x, W1, n);
    k_agg1    <<<(n * 32 + 255) / 256, 256>>>(b1, n);
    k_gemm2   <<<(n + 63) / 64, 256>>>(W2, n);
    k_agg2    <<<(n * 32 + 255) / 256, 256>>>(b2, n);
    k_out     <<<(n + 255) / 256, 256>>>(Wo, bo, (float*)d_out, n);
}

// round 4
// speedup vs baseline: 1.3824x; 1.3824x over previous
#include <cuda_runtime.h>

#define NN      100000
#define EE      1600000
#define INC     165
#define C1      128
#define C2      64

// ---------------- scratch (static device globals; no runtime alloc) ----------------
__device__ int   g_cnt[NN];
__device__ int   g_cur[NN];
__device__ int   g_incl[NN];
__device__ int   g_rowptr[NN + 1];
__device__ int   g_bsum[128];
__device__ float g_dinv[NN];
__device__ int   g_col[EE];
__device__ float g_H1[(size_t)NN * C1];
__device__ float g_A1[(size_t)NN * C1];
__device__ float g_H2[(size_t)NN * C2];

// ---------------- tf32 helpers ----------------
__device__ __forceinline__ unsigned f2tf(float f) {
    unsigned u;
    asm("cvt.rna.tf32.f32 %0, %1;" : "=r"(u) : "f"(f));
    return u;
}

__device__ __forceinline__ void mma_tf32(float4& c,
                                         unsigned a0, unsigned a1, unsigned a2, unsigned a3,
                                         unsigned b0, unsigned b1) {
    asm volatile(
        "mma.sync.aligned.m16n8k8.row.col.f32.tf32.tf32.f32 "
        "{%0,%1,%2,%3}, {%4,%5,%6,%7}, {%8,%9}, {%0,%1,%2,%3};"
        : "+f"(c.x), "+f"(c.y), "+f"(c.z), "+f"(c.w)
        : "r"(a0), "r"(a1), "r"(a2), "r"(a3), "r"(b0), "r"(b1));
}

// ---------------- CSR build ----------------
__global__ void k_zero(int n) {
    int i = blockIdx.x * blockDim.x + threadIdx.x;
    if (i < n) g_cnt[i] = 0;
}

__global__ void k_hist(const int* __restrict__ dst, int e) {
    int i = blockIdx.x * blockDim.x + threadIdx.x;
    if (i < e) atomicAdd(&g_cnt[dst[i]], 1);
}

// block scans 2048 elements (512 threads x 4)
__global__ void k_scan1(int n) {
    __shared__ int s[512];
    int tid  = threadIdx.x;
    int base = blockIdx.x * 2048 + tid * 4;
    int v[4];
    int local = 0;
#pragma unroll
    for (int i = 0; i < 4; i++) {
        int idx = base + i;
        int t = (idx < n) ? g_cnt[idx] : 0;
        v[i] = t; local += t;
    }
    s[tid] = local;
    __syncthreads();
    for (int off = 1; off < 512; off <<= 1) {
        int t = (tid >= off) ? s[tid - off] : 0;
        __syncthreads();
        s[tid] += t;
        __syncthreads();
    }
    int run = s[tid] - local;
#pragma unroll
    for (int i = 0; i < 4; i++) {
        run += v[i];
        int idx = base + i;
        if (idx < n) g_incl[idx] = run;
    }
    if (tid == 511) g_bsum[blockIdx.x] = s[511];
}

__global__ void k_scan2(int nb) {
    __shared__ int s[128];
    int tid = threadIdx.x;
    int v = (tid < nb) ? g_bsum[tid] : 0;
    s[tid] = v;
    __syncthreads();
    for (int off = 1; off < 128; off <<= 1) {
        int t = (tid >= off) ? s[tid - off] : 0;
        __syncthreads();
        s[tid] += t;
        __syncthreads();
    }
    g_bsum[tid] = s[tid] - v;
}

__global__ void k_finalize(int n, int e) {
    int i = blockIdx.x * blockDim.x + threadIdx.x;
    if (i < n) {
        int rp = g_incl[i] - g_cnt[i] + g_bsum[i >> 11];
        g_rowptr[i] = rp;
        g_cur[i]    = rp;                    // seed fill cursor
        g_dinv[i]   = rsqrtf((float)g_cnt[i] + 1.0f);
    }
    if (i == 0) g_rowptr[n] = e;
}

__global__ void k_fill(const int* __restrict__ src, const int* __restrict__ dst, int e) {
    int i = blockIdx.x * blockDim.x + threadIdx.x;
    if (i < e) {
        int p = atomicAdd(&g_cur[dst[i]], 1);
        g_col[p] = src[i];
    }
}

// ---------------- GEMM1: H1 = X @ W1  (TF32 tensor cores) ----------------
// Block tile 128x128, 8 warps (4 m x 2 n), warp tile 32x64, K padded 165->168.
__global__ __launch_bounds__(256) void k_gemm1(const float* __restrict__ X,
                                               const float* __restrict__ W, int n) {
    __shared__ unsigned As[128 * 12];   // [m][k], stride 12 (8 used)
    __shared__ unsigned Bs[8 * 136];    // [k][n], stride 136

    int tid  = threadIdx.x;
    int wid  = tid >> 5;
    int lane = tid & 31;
    int g    = lane >> 2;
    int t    = lane & 3;
    int wm   = (wid & 3) * 32;
    int wn   = (wid >> 2) * 64;
    int rowBase = blockIdx.x * 128;

    float4 C[2][8];
#pragma unroll
    for (int a = 0; a < 2; a++)
#pragma unroll
        for (int b = 0; b < 8; b++) C[a][b] = make_float4(0.f, 0.f, 0.f, 0.f);

    for (int kt = 0; kt < 21; kt++) {
        int k0 = kt * 8;
#pragma unroll
        for (int i = tid; i < 1024; i += 256) {
            int r = i >> 3, kk = i & 7;
            int gr = rowBase + r, gk = k0 + kk;
            float v = (gr < n && gk < INC) ? X[(size_t)gr * INC + gk] : 0.f;
            As[r * 12 + kk] = f2tf(v);
        }
#pragma unroll
        for (int i = tid; i < 1024; i += 256) {
            int kk = i >> 7, c = i & 127;
            int gk = k0 + kk;
            float v = (gk < INC) ? W[(size_t)gk * C1 + c] : 0.f;
            Bs[kk * 136 + c] = f2tf(v);
        }
        __syncthreads();

        unsigned a[2][4];
#pragma unroll
        for (int mg = 0; mg < 2; mg++) {
            int r = wm + mg * 16 + g;
            a[mg][0] = As[r * 12 + t];
            a[mg][1] = As[(r + 8) * 12 + t];
            a[mg][2] = As[r * 12 + t + 4];
            a[mg][3] = As[(r + 8) * 12 + t + 4];
        }
#pragma unroll
        for (int nc = 0; nc < 8; nc++) {
            int cb = wn + nc * 8 + g;
            unsigned b0 = Bs[t * 136 + cb];
            unsigned b1 = Bs[(t + 4) * 136 + cb];
            mma_tf32(C[0][nc], a[0][0], a[0][1], a[0][2], a[0][3], b0, b1);
            mma_tf32(C[1][nc], a[1][0], a[1][1], a[1][2], a[1][3], b0, b1);
        }
        __syncthreads();
    }

#pragma unroll
    for (int mg = 0; mg < 2; mg++) {
        int r = rowBase + wm + mg * 16 + g;
#pragma unroll
        for (int nc = 0; nc < 8; nc++) {
            int c = wn + nc * 8 + 2 * t;
            if (r < n)
                *(float2*)&g_H1[(size_t)r * C1 + c] = make_float2(C[mg][nc].x, C[mg][nc].y);
            if (r + 8 < n)
                *(float2*)&g_H1[(size_t)(r + 8) * C1 + c] = make_float2(C[mg][nc].z, C[mg][nc].w);
        }
    }
}

// ---------------- GEMM2: H2 = A1 @ W2  (TF32 tensor cores) ----------------
// Block tile 128x64, 8 warps each owning 16 rows, warp tile 16x64, K=128.
__global__ __launch_bounds__(256) void k_gemm2(const float* __restrict__ W, int n) {
    __shared__ unsigned As[128 * 12];
    __shared__ unsigned Bs[8 * 72];

    int tid  = threadIdx.x;
    int wid  = tid >> 5;
    int lane = tid & 31;
    int g    = lane >> 2;
    int t    = lane & 3;
    int wm   = wid * 16;
    int rowBase = blockIdx.x * 128;

    float4 C[8];
#pragma unroll
    for (int b = 0; b < 8; b++) C[b] = make_float4(0.f, 0.f, 0.f, 0.f);

    for (int kt = 0; kt < 16; kt++) {
        int k0 = kt * 8;
#pragma unroll
        for (int i = tid; i < 1024; i += 256) {
            int r = i >> 3, kk = i & 7;
            int gr = rowBase + r;
            float v = (gr < n) ? g_A1[(size_t)gr * C1 + k0 + kk] : 0.f;
            As[r * 12 + kk] = f2tf(v);
        }
#pragma unroll
        for (int i = tid; i < 512; i += 256) {
            int kk = i >> 6, c = i & 63;
            Bs[kk * 72 + c] = f2tf(W[(size_t)(k0 + kk) * C2 + c]);
        }
        __syncthreads();

        int r = wm + g;
        unsigned a0 = As[r * 12 + t];
        unsigned a1 = As[(r + 8) * 12 + t];
        unsigned a2 = As[r * 12 + t + 4];
        unsigned a3 = As[(r + 8) * 12 + t + 4];
#pragma unroll
        for (int nc = 0; nc < 8; nc++) {
            int cb = nc * 8 + g;
            unsigned b0 = Bs[t * 72 + cb];
            unsigned b1 = Bs[(t + 4) * 72 + cb];
            mma_tf32(C[nc], a0, a1, a2, a3, b0, b1);
        }
        __syncthreads();
    }

    int r = rowBase + wm + g;
#pragma unroll
    for (int nc = 0; nc < 8; nc++) {
        int c = nc * 8 + 2 * t;
        if (r < n)
            *(float2*)&g_H2[(size_t)r * C2 + c] = make_float2(C[nc].x, C[nc].y);
        if (r + 8 < n)
            *(float2*)&g_H2[(size_t)(r + 8) * C2 + c] = make_float2(C[nc].z, C[nc].w);
    }
}

// ---------------- agg1: warp per dst node, gather from CSR, bias+relu ----------------
__global__ void k_agg1(const float* __restrict__ b, int n) {
    int gidx = blockIdx.x * blockDim.x + threadIdx.x;
    int node = gidx >> 5;
    int lane = gidx & 31;
    if (node >= n) return;
    float di = g_dinv[node];
    float sw = di * di;
    float4 acc = *((const float4*)(g_H1 + (size_t)node * C1) + lane);
    acc.x *= sw; acc.y *= sw; acc.z *= sw; acc.w *= sw;
    int e   = g_rowptr[node];
    int end = g_rowptr[node + 1];
    for (; e + 1 < end; e += 2) {
        int s0 = g_col[e], s1 = g_col[e + 1];
        float w0 = di * g_dinv[s0];
        float w1 = di * g_dinv[s1];
        float4 h0 = *((const float4*)(g_H1 + (size_t)s0 * C1) + lane);
        float4 h1 = *((const float4*)(g_H1 + (size_t)s1 * C1) + lane);
        acc.x += w0 * h0.x + w1 * h1.x;
        acc.y += w0 * h0.y + w1 * h1.y;
        acc.z += w0 * h0.z + w1 * h1.z;
        acc.w += w0 * h0.w + w1 * h1.w;
    }
    if (e < end) {
        int s0 = g_col[e];
        float w0 = di * g_dinv[s0];
        float4 h0 = *((const float4*)(g_H1 + (size_t)s0 * C1) + lane);
        acc.x += w0 * h0.x; acc.y += w0 * h0.y;
        acc.z += w0 * h0.z; acc.w += w0 * h0.w;
    }
    float4 bb = *((const float4*)b + lane);
    float4 o;
    o.x = fmaxf(acc.x + bb.x, 0.f);
    o.y = fmaxf(acc.y + bb.y, 0.f);
    o.z = fmaxf(acc.z + bb.z, 0.f);
    o.w = fmaxf(acc.w + bb.w, 0.f);
    *((float4*)(g_A1 + (size_t)node * C1) + lane) = o;
}

// ---------------- agg2 fused with output projection ----------------
__global__ void k_agg2out(const float* __restrict__ b, const float* __restrict__ Wo,
                          const float* __restrict__ bo, float* __restrict__ out, int n) {
    int gidx = blockIdx.x * blockDim.x + threadIdx.x;
    int node = gidx >> 5;
    int lane = gidx & 31;
    if (node >= n) return;
    float di = g_dinv[node];
    float sw = di * di;
    float2 acc = *((const float2*)(g_H2 + (size_t)node * C2) + lane);
    acc.x *= sw; acc.y *= sw;
    int e   = g_rowptr[node];
    int end = g_rowptr[node + 1];
    for (; e + 1 < end; e += 2) {
        int s0 = g_col[e], s1 = g_col[e + 1];
        float w0 = di * g_dinv[s0];
        float w1 = di * g_dinv[s1];
        float2 h0 = *((const float2*)(g_H2 + (size_t)s0 * C2) + lane);
        float2 h1 = *((const float2*)(g_H2 + (size_t)s1 * C2) + lane);
        acc.x += w0 * h0.x + w1 * h1.x;
        acc.y += w0 * h0.y + w1 * h1.y;
    }
    if (e < end) {
        int s0 = g_col[e];
        float w0 = di * g_dinv[s0];
        float2 h0 = *((const float2*)(g_H2 + (size_t)s0 * C2) + lane);
        acc.x += w0 * h0.x; acc.y += w0 * h0.y;
    }
    float2 bb = *((const float2*)b + lane);
    float ox = fmaxf(acc.x + bb.x, 0.f);
    float oy = fmaxf(acc.y + bb.y, 0.f);
    // project: lane holds channels 2*lane, 2*lane+1
    int ch = 2 * lane;
    float d0 = ox * Wo[ch * 2]     + oy * Wo[(ch + 1) * 2];
    float d1 = ox * Wo[ch * 2 + 1] + oy * Wo[(ch + 1) * 2 + 1];
#pragma unroll
    for (int m = 16; m > 0; m >>= 1) {
        d0 += __shfl_xor_sync(0xFFFFFFFFu, d0, m);
        d1 += __shfl_xor_sync(0xFFFFFFFFu, d1, m);
    }
    if (lane == 0) {
        float2 r;
        r.x = d0 + bo[0];
        r.y = d1 + bo[1];
        ((float2*)out)[node] = r;
    }
}

// ---------------- launch ----------------
extern "C" void kernel_launch(void* const* d_in, const int* in_sizes, int n_in,
                              void* d_out, int out_size) {
    const float* x   = (const float*)d_in[0];
    const int*   ei  = (const int*)  d_in[1];
    const float* W1  = (const float*)d_in[2];
    const float* b1  = (const float*)d_in[3];
    const float* W2  = (const float*)d_in[4];
    const float* b2  = (const float*)d_in[5];
    const float* Wo  = (const float*)d_in[6];
    const float* bo  = (const float*)d_in[7];

    int n = in_sizes[0] / INC;
    int e = in_sizes[1] / 2;
    const int* src = ei;
    const int* dst = ei + e;

    int nb = (n + 2047) / 2048;

    k_zero    <<<(n + 255) / 256, 256>>>(n);
    k_hist    <<<(e + 255) / 256, 256>>>(dst, e);
    k_scan1   <<<nb, 512>>>(n);
    k_scan2   <<<1, 128>>>(nb);
    k_finalize<<<(n + 255) / 256, 256>>>(n, e);
    k_fill    <<<(e + 255) / 256, 256>>>(src, dst, e);

    k_gemm1   <<<(n + 127) / 128, 256>>>(x, W1, n);
    k_agg1    <<<(n * 32 + 255) / 256, 256>>>(b1, n);
    k_gemm2   <<<(n + 127) / 128, 256>>>(W2, n);
    k_agg2out <<<(n * 32 + 255) / 256, 256>>>(b2, Wo, bo, (float*)d_out, n);
}

// round 5
// speedup vs baseline: 1.4103x; 1.0201x over previous
#include <cuda_runtime.h>
#include <cuda_fp16.h>

#define NN      100000
#define EE      1600000
#define INC     165
#define C1      128
#define C2      64

// ---------------- scratch (static device globals; no runtime alloc) ----------------
__device__ int    g_cnt[NN];
__device__ int    g_cur[NN];
__device__ int    g_incl[NN];
__device__ int    g_rowptr[NN + 1];
__device__ int    g_bsum[128];
__device__ float  g_dinv[NN];
__device__ int    g_col[EE];
__device__ float  g_ws[EE];                  // per-edge weight = dinv[src]
__device__ __half g_H1h[(size_t)NN * C1];    // fp16 gather array (layer 1)
__device__ float  g_A1[(size_t)NN * C1];
__device__ __half g_H2h[(size_t)NN * C2];    // fp16 gather array (layer 2)

// ---------------- tf32 helpers ----------------
__device__ __forceinline__ unsigned f2tf(float f) {
    unsigned u;
    asm("cvt.rna.tf32.f32 %0, %1;" : "=r"(u) : "f"(f));
    return u;
}

__device__ __forceinline__ void mma_tf32(float4& c,
                                         unsigned a0, unsigned a1, unsigned a2, unsigned a3,
                                         unsigned b0, unsigned b1) {
    asm volatile(
        "mma.sync.aligned.m16n8k8.row.col.f32.tf32.tf32.f32 "
        "{%0,%1,%2,%3}, {%4,%5,%6,%7}, {%8,%9}, {%0,%1,%2,%3};"
        : "+f"(c.x), "+f"(c.y), "+f"(c.z), "+f"(c.w)
        : "r"(a0), "r"(a1), "r"(a2), "r"(a3), "r"(b0), "r"(b1));
}

// ---------------- CSR build ----------------
__global__ void k_zero(int n) {
    int i = blockIdx.x * blockDim.x + threadIdx.x;
    if (i < n) g_cnt[i] = 0;
}

__global__ void k_hist(const int* __restrict__ dst, int e) {
    int i = blockIdx.x * blockDim.x + threadIdx.x;
    if (i < e) atomicAdd(&g_cnt[dst[i]], 1);
}

__global__ void k_scan1(int n) {
    __shared__ int s[512];
    int tid  = threadIdx.x;
    int base = blockIdx.x * 2048 + tid * 4;
    int v[4];
    int local = 0;
#pragma unroll
    for (int i = 0; i < 4; i++) {
        int idx = base + i;
        int t = (idx < n) ? g_cnt[idx] : 0;
        v[i] = t; local += t;
    }
    s[tid] = local;
    __syncthreads();
    for (int off = 1; off < 512; off <<= 1) {
        int t = (tid >= off) ? s[tid - off] : 0;
        __syncthreads();
        s[tid] += t;
        __syncthreads();
    }
    int run = s[tid] - local;
#pragma unroll
    for (int i = 0; i < 4; i++) {
        run += v[i];
        int idx = base + i;
        if (idx < n) g_incl[idx] = run;
    }
    if (tid == 511) g_bsum[blockIdx.x] = s[511];
}

__global__ void k_scan2(int nb) {
    __shared__ int s[128];
    int tid = threadIdx.x;
    int v = (tid < nb) ? g_bsum[tid] : 0;
    s[tid] = v;
    __syncthreads();
    for (int off = 1; off < 128; off <<= 1) {
        int t = (tid >= off) ? s[tid - off] : 0;
        __syncthreads();
        s[tid] += t;
        __syncthreads();
    }
    g_bsum[tid] = s[tid] - v;
}

__global__ void k_finalize(int n, int e) {
    int i = blockIdx.x * blockDim.x + threadIdx.x;
    if (i < n) {
        int rp = g_incl[i] - g_cnt[i] + g_bsum[i >> 11];
        g_rowptr[i] = rp;
        g_cur[i]    = rp;
        g_dinv[i]   = rsqrtf((float)g_cnt[i] + 1.0f);
    }
    if (i == 0) g_rowptr[n] = e;
}

__global__ void k_fill(const int* __restrict__ src, const int* __restrict__ dst, int e) {
    int i = blockIdx.x * blockDim.x + threadIdx.x;
    if (i < e) {
        int s = src[i];
        int p = atomicAdd(&g_cur[dst[i]], 1);
        g_col[p] = s;
        g_ws[p]  = g_dinv[s];
    }
}

// ---------------- GEMM1: H1h = fp16(X @ W1)  (TF32 tensor cores) ----------------
__global__ __launch_bounds__(256) void k_gemm1(const float* __restrict__ X,
                                               const float* __restrict__ W, int n) {
    __shared__ unsigned As[128 * 12];
    __shared__ unsigned Bs[8 * 136];

    int tid  = threadIdx.x;
    int wid  = tid >> 5;
    int lane = tid & 31;
    int g    = lane >> 2;
    int t    = lane & 3;
    int wm   = (wid & 3) * 32;
    int wn   = (wid >> 2) * 64;
    int rowBase = blockIdx.x * 128;

    float4 C[2][8];
#pragma unroll
    for (int a = 0; a < 2; a++)
#pragma unroll
        for (int b = 0; b < 8; b++) C[a][b] = make_float4(0.f, 0.f, 0.f, 0.f);

    for (int kt = 0; kt < 21; kt++) {
        int k0 = kt * 8;
#pragma unroll
        for (int i = tid; i < 1024; i += 256) {
            int r = i >> 3, kk = i & 7;
            int gr = rowBase + r, gk = k0 + kk;
            float v = (gr < n && gk < INC) ? X[(size_t)gr * INC + gk] : 0.f;
            As[r * 12 + kk] = f2tf(v);
        }
#pragma unroll
        for (int i = tid; i < 1024; i += 256) {
            int kk = i >> 7, c = i & 127;
            int gk = k0 + kk;
            float v = (gk < INC) ? W[(size_t)gk * C1 + c] : 0.f;
            Bs[kk * 136 + c] = f2tf(v);
        }
        __syncthreads();

        unsigned a[2][4];
#pragma unroll
        for (int mg = 0; mg < 2; mg++) {
            int r = wm + mg * 16 + g;
            a[mg][0] = As[r * 12 + t];
            a[mg][1] = As[(r + 8) * 12 + t];
            a[mg][2] = As[r * 12 + t + 4];
            a[mg][3] = As[(r + 8) * 12 + t + 4];
        }
#pragma unroll
        for (int nc = 0; nc < 8; nc++) {
            int cb = wn + nc * 8 + g;
            unsigned b0 = Bs[t * 136 + cb];
            unsigned b1 = Bs[(t + 4) * 136 + cb];
            mma_tf32(C[0][nc], a[0][0], a[0][1], a[0][2], a[0][3], b0, b1);
            mma_tf32(C[1][nc], a[1][0], a[1][1], a[1][2], a[1][3], b0, b1);
        }
        __syncthreads();
    }

#pragma unroll
    for (int mg = 0; mg < 2; mg++) {
        int r = rowBase + wm + mg * 16 + g;
#pragma unroll
        for (int nc = 0; nc < 8; nc++) {
            int c = wn + nc * 8 + 2 * t;
            if (r < n)
                *(__half2*)&g_H1h[(size_t)r * C1 + c] =
                    __floats2half2_rn(C[mg][nc].x, C[mg][nc].y);
            if (r + 8 < n)
                *(__half2*)&g_H1h[(size_t)(r + 8) * C1 + c] =
                    __floats2half2_rn(C[mg][nc].z, C[mg][nc].w);
        }
    }
}

// ---------------- GEMM2: H2h = fp16(A1 @ W2)  (3xTF32 split for ~fp32 accuracy) ----
__global__ __launch_bounds__(256) void k_gemm2(const float* __restrict__ W, int n) {
    __shared__ unsigned Ah[128 * 12];
    __shared__ unsigned Al[128 * 12];
    __shared__ unsigned Bh[8 * 72];
    __shared__ unsigned Bl[8 * 72];

    int tid  = threadIdx.x;
    int wid  = tid >> 5;
    int lane = tid & 31;
    int g    = lane >> 2;
    int t    = lane & 3;
    int wm   = wid * 16;
    int rowBase = blockIdx.x * 128;

    float4 C[8];
#pragma unroll
    for (int b = 0; b < 8; b++) C[b] = make_float4(0.f, 0.f, 0.f, 0.f);

    for (int kt = 0; kt < 16; kt++) {
        int k0 = kt * 8;
#pragma unroll
        for (int i = tid; i < 1024; i += 256) {
            int r = i >> 3, kk = i & 7;
            int gr = rowBase + r;
            float v = (gr < n) ? g_A1[(size_t)gr * C1 + k0 + kk] : 0.f;
            unsigned hi = f2tf(v);
            Ah[r * 12 + kk] = hi;
            Al[r * 12 + kk] = f2tf(v - __uint_as_float(hi));
        }
#pragma unroll
        for (int i = tid; i < 512; i += 256) {
            int kk = i >> 6, c = i & 63;
            float v = W[(size_t)(k0 + kk) * C2 + c];
            unsigned hi = f2tf(v);
            Bh[kk * 72 + c] = hi;
            Bl[kk * 72 + c] = f2tf(v - __uint_as_float(hi));
        }
        __syncthreads();

        int r = wm + g;
        unsigned ah0 = Ah[r * 12 + t];
        unsigned ah1 = Ah[(r + 8) * 12 + t];
        unsigned ah2 = Ah[r * 12 + t + 4];
        unsigned ah3 = Ah[(r + 8) * 12 + t + 4];
        unsigned al0 = Al[r * 12 + t];
        unsigned al1 = Al[(r + 8) * 12 + t];
        unsigned al2 = Al[r * 12 + t + 4];
        unsigned al3 = Al[(r + 8) * 12 + t + 4];
#pragma unroll
        for (int nc = 0; nc < 8; nc++) {
            int cb = nc * 8 + g;
            unsigned bh0 = Bh[t * 72 + cb];
            unsigned bh1 = Bh[(t + 4) * 72 + cb];
            unsigned bl0 = Bl[t * 72 + cb];
            unsigned bl1 = Bl[(t + 4) * 72 + cb];
            mma_tf32(C[nc], ah0, ah1, ah2, ah3, bh0, bh1);
            mma_tf32(C[nc], al0, al1, al2, al3, bh0, bh1);
            mma_tf32(C[nc], ah0, ah1, ah2, ah3, bl0, bl1);
        }
        __syncthreads();
    }

    int r = rowBase + wm + g;
#pragma unroll
    for (int nc = 0; nc < 8; nc++) {
        int c = nc * 8 + 2 * t;
        if (r < n)
            *(__half2*)&g_H2h[(size_t)r * C2 + c] = __floats2half2_rn(C[nc].x, C[nc].y);
        if (r + 8 < n)
            *(__half2*)&g_H2h[(size_t)(r + 8) * C2 + c] = __floats2half2_rn(C[nc].z, C[nc].w);
    }
}

// ---------------- agg1: warp per dst node, fp16 gathers, bias+relu -> A1 (fp32) ----
__global__ void k_agg1(const float* __restrict__ b, int n) {
    int gidx = blockIdx.x * blockDim.x + threadIdx.x;
    int node = gidx >> 5;
    int lane = gidx & 31;
    if (node >= n) return;
    float di = g_dinv[node];

    // self term: di * h[node]  (outer di applied at the end)
    uint2 v = *(const uint2*)(g_H1h + (size_t)node * C1 + 4 * lane);
    float2 p0 = __half22float2(*(__half2*)&v.x);
    float2 p1 = __half22float2(*(__half2*)&v.y);
    float a0 = di * p0.x, a1 = di * p0.y, a2 = di * p1.x, a3 = di * p1.y;

    int e   = g_rowptr[node];
    int end = g_rowptr[node + 1];
    for (; e + 1 < end; e += 2) {
        int   s0 = g_col[e],  s1 = g_col[e + 1];
        float w0 = g_ws[e],   w1 = g_ws[e + 1];
        uint2 u0 = *(const uint2*)(g_H1h + (size_t)s0 * C1 + 4 * lane);
        uint2 u1 = *(const uint2*)(g_H1h + (size_t)s1 * C1 + 4 * lane);
        float2 q0 = __half22float2(*(__half2*)&u0.x);
        float2 q1 = __half22float2(*(__half2*)&u0.y);
        float2 r0 = __half22float2(*(__half2*)&u1.x);
        float2 r1 = __half22float2(*(__half2*)&u1.y);
        a0 += w0 * q0.x + w1 * r0.x;
        a1 += w0 * q0.y + w1 * r0.y;
        a2 += w0 * q1.x + w1 * r1.x;
        a3 += w0 * q1.y + w1 * r1.y;
    }
    if (e < end) {
        int   s0 = g_col[e];
        float w0 = g_ws[e];
        uint2 u0 = *(const uint2*)(g_H1h + (size_t)s0 * C1 + 4 * lane);
        float2 q0 = __half22float2(*(__half2*)&u0.x);
        float2 q1 = __half22float2(*(__half2*)&u0.y);
        a0 += w0 * q0.x; a1 += w0 * q0.y;
        a2 += w0 * q1.x; a3 += w0 * q1.y;
    }
    float4 bb = *((const float4*)b + lane);
    float4 o;
    o.x = fmaxf(di * a0 + bb.x, 0.f);
    o.y = fmaxf(di * a1 + bb.y, 0.f);
    o.z = fmaxf(di * a2 + bb.z, 0.f);
    o.w = fmaxf(di * a3 + bb.w, 0.f);
    *((float4*)(g_A1 + (size_t)node * C1) + lane) = o;
}

// ---------------- agg2 (fp16 gathers) fused with output projection ----------------
__global__ void k_agg2out(const float* __restrict__ b, const float* __restrict__ Wo,
                          const float* __restrict__ bo, float* __restrict__ out, int n) {
    int gidx = blockIdx.x * blockDim.x + threadIdx.x;
    int node = gidx >> 5;
    int lane = gidx & 31;
    if (node >= n) return;
    float di = g_dinv[node];

    float2 p = __half22float2(*(const __half2*)(g_H2h + (size_t)node * C2 + 2 * lane));
    float a0 = di * p.x, a1 = di * p.y;

    int e   = g_rowptr[node];
    int end = g_rowptr[node + 1];
    for (; e + 1 < end; e += 2) {
        int   s0 = g_col[e],  s1 = g_col[e + 1];
        float w0 = g_ws[e],   w1 = g_ws[e + 1];
        float2 q = __half22float2(*(const __half2*)(g_H2h + (size_t)s0 * C2 + 2 * lane));
        float2 r = __half22float2(*(const __half2*)(g_H2h + (size_t)s1 * C2 + 2 * lane));
        a0 += w0 * q.x + w1 * r.x;
        a1 += w0 * q.y + w1 * r.y;
    }
    if (e < end) {
        int   s0 = g_col[e];
        float w0 = g_ws[e];
        float2 q = __half22float2(*(const __half2*)(g_H2h + (size_t)s0 * C2 + 2 * lane));
        a0 += w0 * q.x; a1 += w0 * q.y;
    }
    float2 bb = *((const float2*)b + lane);
    float ox = fmaxf(di * a0 + bb.x, 0.f);
    float oy = fmaxf(di * a1 + bb.y, 0.f);

    int ch = 2 * lane;
    float d0 = ox * Wo[ch * 2]     + oy * Wo[(ch + 1) * 2];
    float d1 = ox * Wo[ch * 2 + 1] + oy * Wo[(ch + 1) * 2 + 1];
#pragma unroll
    for (int m = 16; m > 0; m >>= 1) {
        d0 += __shfl_xor_sync(0xFFFFFFFFu, d0, m);
        d1 += __shfl_xor_sync(0xFFFFFFFFu, d1, m);
    }
    if (lane == 0) {
        float2 r;
        r.x = d0 + bo[0];
        r.y = d1 + bo[1];
        ((float2*)out)[node] = r;
    }
}

// ---------------- launch ----------------
extern "C" void kernel_launch(void* const* d_in, const int* in_sizes, int n_in,
                              void* d_out, int out_size) {
    const float* x   = (const float*)d_in[0];
    const int*   ei  = (const int*)  d_in[1];
    const float* W1  = (const float*)d_in[2];
    const float* b1  = (const float*)d_in[3];
    const float* W2  = (const float*)d_in[4];
    const float* b2  = (const float*)d_in[5];
    const float* Wo  = (const float*)d_in[6];
    const float* bo  = (const float*)d_in[7];

    int n = in_sizes[0] / INC;
    int e = in_sizes[1] / 2;
    const int* src = ei;
    const int* dst = ei + e;

    int nb = (n + 2047) / 2048;

    k_zero    <<<(n + 255) / 256, 256>>>(n);
    k_hist    <<<(e + 255) / 256, 256>>>(dst, e);
    k_scan1   <<<nb, 512>>>(n);
    k_scan2   <<<1, 128>>>(nb);
    k_finalize<<<(n + 255) / 256, 256>>>(n, e);
    k_fill    <<<(e + 255) / 256, 256>>>(src, dst, e);

    k_gemm1   <<<(n + 127) / 128, 256>>>(x, W1, n);
    k_agg1    <<<(n * 32 + 255) / 256, 256>>>(b1, n);
    k_gemm2   <<<(n + 127) / 128, 256>>>(W2, n);
    k_agg2out <<<(n * 32 + 255) / 256, 256>>>(b2, Wo, bo, (float*)d_out, n);
}

// round 6
// speedup vs baseline: 1.4525x; 1.0299x over previous
#include <cuda_runtime.h>
#include <cuda_fp16.h>

#define NN      100000
#define EE      1600000
#define INC     165
#define C1      128
#define C2      64

// ---------------- scratch (static device globals; no runtime alloc) ----------------
__device__ int    g_cnt[NN];
__device__ int    g_cur[NN];
__device__ int    g_incl[NN];
__device__ int    g_rowptr[NN + 1];
__device__ int    g_bsum[128];
__device__ float  g_dinv[NN];
__device__ uint2  g_edge[EE];                // .x = src idx, .y = bits(dinv[src])
__device__ __half g_H1h[(size_t)NN * C1];
__device__ float  g_A1[(size_t)NN * C1];
__device__ __half g_H2h[(size_t)NN * C2];

// ---------------- tf32 helpers ----------------
__device__ __forceinline__ unsigned f2tf(float f) {
    unsigned u;
    asm("cvt.rna.tf32.f32 %0, %1;" : "=r"(u) : "f"(f));
    return u;
}

__device__ __forceinline__ void mma_tf32(float4& c,
                                         unsigned a0, unsigned a1, unsigned a2, unsigned a3,
                                         unsigned b0, unsigned b1) {
    asm volatile(
        "mma.sync.aligned.m16n8k8.row.col.f32.tf32.tf32.f32 "
        "{%0,%1,%2,%3}, {%4,%5,%6,%7}, {%8,%9}, {%0,%1,%2,%3};"
        : "+f"(c.x), "+f"(c.y), "+f"(c.z), "+f"(c.w)
        : "r"(a0), "r"(a1), "r"(a2), "r"(a3), "r"(b0), "r"(b1));
}

// ---------------- CSR build ----------------
__global__ void k_zero(int n) {
    int i = blockIdx.x * blockDim.x + threadIdx.x;
    if (i < n) g_cnt[i] = 0;
}

__global__ void k_hist(const int* __restrict__ dst, int e) {
    int i = blockIdx.x * blockDim.x + threadIdx.x;
    if (i < e) atomicAdd(&g_cnt[dst[i]], 1);
}

__global__ void k_scan1(int n) {
    __shared__ int s[512];
    int tid  = threadIdx.x;
    int base = blockIdx.x * 2048 + tid * 4;
    int v[4];
    int local = 0;
#pragma unroll
    for (int i = 0; i < 4; i++) {
        int idx = base + i;
        int t = (idx < n) ? g_cnt[idx] : 0;
        v[i] = t; local += t;
    }
    s[tid] = local;
    __syncthreads();
    for (int off = 1; off < 512; off <<= 1) {
        int t = (tid >= off) ? s[tid - off] : 0;
        __syncthreads();
        s[tid] += t;
        __syncthreads();
    }
    int run = s[tid] - local;
#pragma unroll
    for (int i = 0; i < 4; i++) {
        run += v[i];
        int idx = base + i;
        if (idx < n) g_incl[idx] = run;
    }
    if (tid == 511) g_bsum[blockIdx.x] = s[511];
}

__global__ void k_scan2(int nb) {
    __shared__ int s[128];
    int tid = threadIdx.x;
    int v = (tid < nb) ? g_bsum[tid] : 0;
    s[tid] = v;
    __syncthreads();
    for (int off = 1; off < 128; off <<= 1) {
        int t = (tid >= off) ? s[tid - off] : 0;
        __syncthreads();
        s[tid] += t;
        __syncthreads();
    }
    g_bsum[tid] = s[tid] - v;
}

__global__ void k_finalize(int n, int e) {
    int i = blockIdx.x * blockDim.x + threadIdx.x;
    if (i < n) {
        int rp = g_incl[i] - g_cnt[i] + g_bsum[i >> 11];
        g_rowptr[i] = rp;
        g_cur[i]    = rp;
        g_dinv[i]   = rsqrtf((float)g_cnt[i] + 1.0f);
    }
    if (i == 0) g_rowptr[n] = e;
}

__global__ void k_fill(const int* __restrict__ src, const int* __restrict__ dst, int e) {
    int i = blockIdx.x * blockDim.x + threadIdx.x;
    if (i < e) {
        int s = src[i];
        int p = atomicAdd(&g_cur[dst[i]], 1);
        g_edge[p] = make_uint2((unsigned)s, __float_as_uint(g_dinv[s]));
    }
}

// ---------------- GEMM1: H1h = fp16(X @ W1)  (TF32, K-tile 32) ----------------
__global__ __launch_bounds__(256) void k_gemm1(const float* __restrict__ X,
                                               const float* __restrict__ W, int n) {
    __shared__ unsigned As[128 * 33];   // [m][k] stride 33
    __shared__ unsigned Bs[32 * 136];   // [k][n] stride 136

    int tid  = threadIdx.x;
    int wid  = tid >> 5;
    int lane = tid & 31;
    int g    = lane >> 2;
    int t    = lane & 3;
    int wm   = (wid & 3) * 32;
    int wn   = (wid >> 2) * 64;
    int rowBase = blockIdx.x * 128;

    float4 C[2][8];
#pragma unroll
    for (int a = 0; a < 2; a++)
#pragma unroll
        for (int b = 0; b < 8; b++) C[a][b] = make_float4(0.f, 0.f, 0.f, 0.f);

    for (int kt = 0; kt < 6; kt++) {        // 6*32 = 192 >= 165
        int k0 = kt * 32;
#pragma unroll
        for (int i = tid; i < 4096; i += 256) {
            int r = i >> 5, kk = i & 31;
            int gr = rowBase + r, gk = k0 + kk;
            float v = (gr < n && gk < INC) ? X[(size_t)gr * INC + gk] : 0.f;
            As[r * 33 + kk] = f2tf(v);
        }
#pragma unroll
        for (int i = tid; i < 4096; i += 256) {
            int kk = i >> 7, c = i & 127;
            int gk = k0 + kk;
            float v = (gk < INC) ? W[(size_t)gk * C1 + c] : 0.f;
            Bs[kk * 136 + c] = f2tf(v);
        }
        __syncthreads();

#pragma unroll
        for (int ks = 0; ks < 4; ks++) {
            int kb = ks * 8;
            unsigned a[2][4];
#pragma unroll
            for (int mg = 0; mg < 2; mg++) {
                int r = wm + mg * 16 + g;
                a[mg][0] = As[r * 33 + kb + t];
                a[mg][1] = As[(r + 8) * 33 + kb + t];
                a[mg][2] = As[r * 33 + kb + t + 4];
                a[mg][3] = As[(r + 8) * 33 + kb + t + 4];
            }
#pragma unroll
            for (int nc = 0; nc < 8; nc++) {
                int cb = wn + nc * 8 + g;
                unsigned b0 = Bs[(kb + t) * 136 + cb];
                unsigned b1 = Bs[(kb + t + 4) * 136 + cb];
                mma_tf32(C[0][nc], a[0][0], a[0][1], a[0][2], a[0][3], b0, b1);
                mma_tf32(C[1][nc], a[1][0], a[1][1], a[1][2], a[1][3], b0, b1);
            }
        }
        __syncthreads();
    }

#pragma unroll
    for (int mg = 0; mg < 2; mg++) {
        int r = rowBase + wm + mg * 16 + g;
#pragma unroll
        for (int nc = 0; nc < 8; nc++) {
            int c = wn + nc * 8 + 2 * t;
            if (r < n)
                *(__half2*)&g_H1h[(size_t)r * C1 + c] =
                    __floats2half2_rn(C[mg][nc].x, C[mg][nc].y);
            if (r + 8 < n)
                *(__half2*)&g_H1h[(size_t)(r + 8) * C1 + c] =
                    __floats2half2_rn(C[mg][nc].z, C[mg][nc].w);
        }
    }
}

// ---------------- GEMM2: H2h = fp16(A1 @ W2)  (TF32, K-tile 32) ----------------
__global__ __launch_bounds__(256) void k_gemm2(const float* __restrict__ W, int n) {
    __shared__ unsigned As[128 * 33];
    __shared__ unsigned Bs[32 * 72];

    int tid  = threadIdx.x;
    int wid  = tid >> 5;
    int lane = tid & 31;
    int g    = lane >> 2;
    int t    = lane & 3;
    int wm   = wid * 16;
    int rowBase = blockIdx.x * 128;

    float4 C[8];
#pragma unroll
    for (int b = 0; b < 8; b++) C[b] = make_float4(0.f, 0.f, 0.f, 0.f);

    for (int kt = 0; kt < 4; kt++) {
        int k0 = kt * 32;
#pragma unroll
        for (int i = tid; i < 4096; i += 256) {
            int r = i >> 5, kk = i & 31;
            int gr = rowBase + r;
            float v = (gr < n) ? g_A1[(size_t)gr * C1 + k0 + kk] : 0.f;
            As[r * 33 + kk] = f2tf(v);
        }
#pragma unroll
        for (int i = tid; i < 2048; i += 256) {
            int kk = i >> 6, c = i & 63;
            Bs[kk * 72 + c] = f2tf(W[(size_t)(k0 + kk) * C2 + c]);
        }
        __syncthreads();

#pragma unroll
        for (int ks = 0; ks < 4; ks++) {
            int kb = ks * 8;
            int r = wm + g;
            unsigned a0 = As[r * 33 + kb + t];
            unsigned a1 = As[(r + 8) * 33 + kb + t];
            unsigned a2 = As[r * 33 + kb + t + 4];
            unsigned a3 = As[(r + 8) * 33 + kb + t + 4];
#pragma unroll
            for (int nc = 0; nc < 8; nc++) {
                int cb = nc * 8 + g;
                unsigned b0 = Bs[(kb + t) * 72 + cb];
                unsigned b1 = Bs[(kb + t + 4) * 72 + cb];
                mma_tf32(C[nc], a0, a1, a2, a3, b0, b1);
            }
        }
        __syncthreads();
    }

    int r = rowBase + wm + g;
#pragma unroll
    for (int nc = 0; nc < 8; nc++) {
        int c = nc * 8 + 2 * t;
        if (r < n)
            *(__half2*)&g_H2h[(size_t)r * C2 + c] = __floats2half2_rn(C[nc].x, C[nc].y);
        if (r + 8 < n)
            *(__half2*)&g_H2h[(size_t)(r + 8) * C2 + c] = __floats2half2_rn(C[nc].z, C[nc].w);
    }
}

// ---------------- agg1: warp per dst node, fp16 gathers (MLP=4), bias+relu ----------
__global__ void k_agg1(const float* __restrict__ b, int n) {
    int gidx = blockIdx.x * blockDim.x + threadIdx.x;
    int node = gidx >> 5;
    int lane = gidx & 31;
    if (node >= n) return;
    float di = g_dinv[node];

    uint2 v = *(const uint2*)(g_H1h + (size_t)node * C1 + 4 * lane);
    float2 p0 = __half22float2(*(__half2*)&v.x);
    float2 p1 = __half22float2(*(__half2*)&v.y);
    float a0 = di * p0.x, a1 = di * p0.y, a2 = di * p1.x, a3 = di * p1.y;

    int e   = g_rowptr[node];
    int end = g_rowptr[node + 1];
    for (; e + 3 < end; e += 4) {
        uint2 e0 = g_edge[e],     e1 = g_edge[e + 1];
        uint2 e2 = g_edge[e + 2], e3 = g_edge[e + 3];
        uint2 u0 = *(const uint2*)(g_H1h + (size_t)e0.x * C1 + 4 * lane);
        uint2 u1 = *(const uint2*)(g_H1h + (size_t)e1.x * C1 + 4 * lane);
        uint2 u2 = *(const uint2*)(g_H1h + (size_t)e2.x * C1 + 4 * lane);
        uint2 u3 = *(const uint2*)(g_H1h + (size_t)e3.x * C1 + 4 * lane);
        float w0 = __uint_as_float(e0.y), w1 = __uint_as_float(e1.y);
        float w2 = __uint_as_float(e2.y), w3 = __uint_as_float(e3.y);
        float2 q;
        q = __half22float2(*(__half2*)&u0.x); a0 += w0 * q.x; a1 += w0 * q.y;
        q = __half22float2(*(__half2*)&u0.y); a2 += w0 * q.x; a3 += w0 * q.y;
        q = __half22float2(*(__half2*)&u1.x); a0 += w1 * q.x; a1 += w1 * q.y;
        q = __half22float2(*(__half2*)&u1.y); a2 += w1 * q.x; a3 += w1 * q.y;
        q = __half22float2(*(__half2*)&u2.x); a0 += w2 * q.x; a1 += w2 * q.y;
        q = __half22float2(*(__half2*)&u2.y); a2 += w2 * q.x; a3 += w2 * q.y;
        q = __half22float2(*(__half2*)&u3.x); a0 += w3 * q.x; a1 += w3 * q.y;
        q = __half22float2(*(__half2*)&u3.y); a2 += w3 * q.x; a3 += w3 * q.y;
    }
    for (; e < end; e++) {
        uint2 e0 = g_edge[e];
        float w0 = __uint_as_float(e0.y);
        uint2 u0 = *(const uint2*)(g_H1h + (size_t)e0.x * C1 + 4 * lane);
        float2 q;
        q = __half22float2(*(__half2*)&u0.x); a0 += w0 * q.x; a1 += w0 * q.y;
        q = __half22float2(*(__half2*)&u0.y); a2 += w0 * q.x; a3 += w0 * q.y;
    }
    float4 bb = *((const float4*)b + lane);
    float4 o;
    o.x = fmaxf(di * a0 + bb.x, 0.f);
    o.y = fmaxf(di * a1 + bb.y, 0.f);
    o.z = fmaxf(di * a2 + bb.z, 0.f);
    o.w = fmaxf(di * a3 + bb.w, 0.f);
    *((float4*)(g_A1 + (size_t)node * C1) + lane) = o;
}

// ---------------- agg2 (fp16 gathers, MLP=4) fused with output projection ----------
__global__ void k_agg2out(const float* __restrict__ b, const float* __restrict__ Wo,
                          const float* __restrict__ bo, float* __restrict__ out, int n) {
    int gidx = blockIdx.x * blockDim.x + threadIdx.x;
    int node = gidx >> 5;
    int lane = gidx & 31;
    if (node >= n) return;
    float di = g_dinv[node];

    float2 p = __half22float2(*(const __half2*)(g_H2h + (size_t)node * C2 + 2 * lane));
    float a0 = di * p.x, a1 = di * p.y;

    int e   = g_rowptr[node];
    int end = g_rowptr[node + 1];
    for (; e + 3 < end; e += 4) {
        uint2 e0 = g_edge[e],     e1 = g_edge[e + 1];
        uint2 e2 = g_edge[e + 2], e3 = g_edge[e + 3];
        __half2 h0 = *(const __half2*)(g_H2h + (size_t)e0.x * C2 + 2 * lane);
        __half2 h1 = *(const __half2*)(g_H2h + (size_t)e1.x * C2 + 2 * lane);
        __half2 h2 = *(const __half2*)(g_H2h + (size_t)e2.x * C2 + 2 * lane);
        __half2 h3 = *(const __half2*)(g_H2h + (size_t)e3.x * C2 + 2 * lane);
        float w0 = __uint_as_float(e0.y), w1 = __uint_as_float(e1.y);
        float w2 = __uint_as_float(e2.y), w3 = __uint_as_float(e3.y);
        float2 q;
        q = __half22float2(h0); a0 += w0 * q.x; a1 += w0 * q.y;
        q = __half22float2(h1); a0 += w1 * q.x; a1 += w1 * q.y;
        q = __half22float2(h2); a0 += w2 * q.x; a1 += w2 * q.y;
        q = __half22float2(h3); a0 += w3 * q.x; a1 += w3 * q.y;
    }
    for (; e < end; e++) {
        uint2 e0 = g_edge[e];
        float w0 = __uint_as_float(e0.y);
        float2 q = __half22float2(*(const __half2*)(g_H2h + (size_t)e0.x * C2 + 2 * lane));
        a0 += w0 * q.x; a1 += w0 * q.y;
    }
    float2 bb = *((const float2*)b + lane);
    float ox = fmaxf(di * a0 + bb.x, 0.f);
    float oy = fmaxf(di * a1 + bb.y, 0.f);

    int ch = 2 * lane;
    float d0 = ox * Wo[ch * 2]     + oy * Wo[(ch + 1) * 2];
    float d1 = ox * Wo[ch * 2 + 1] + oy * Wo[(ch + 1) * 2 + 1];
#pragma unroll
    for (int m = 16; m > 0; m >>= 1) {
        d0 += __shfl_xor_sync(0xFFFFFFFFu, d0, m);
        d1 += __shfl_xor_sync(0xFFFFFFFFu, d1, m);
    }
    if (lane == 0) {
        float2 r;
        r.x = d0 + bo[0];
        r.y = d1 + bo[1];
        ((float2*)out)[node] = r;
    }
}

// ---------------- launch ----------------
extern "C" void kernel_launch(void* const* d_in, const int* in_sizes, int n_in,
                              void* d_out, int out_size) {
    const float* x   = (const float*)d_in[0];
    const int*   ei  = (const int*)  d_in[1];
    const float* W1  = (const float*)d_in[2];
    const float* b1  = (const float*)d_in[3];
    const float* W2  = (const float*)d_in[4];
    const float* b2  = (const float*)d_in[5];
    const float* Wo  = (const float*)d_in[6];
    const float* bo  = (const float*)d_in[7];

    int n = in_sizes[0] / INC;
    int e = in_sizes[1] / 2;
    const int* src = ei;
    const int* dst = ei + e;

    int nb = (n + 2047) / 2048;

    k_zero    <<<(n + 255) / 256, 256>>>(n);
    k_hist    <<<(e + 255) / 256, 256>>>(dst, e);
    k_scan1   <<<nb, 512>>>(n);
    k_scan2   <<<1, 128>>>(nb);
    k_finalize<<<(n + 255) / 256, 256>>>(n, e);
    k_fill    <<<(e + 255) / 256, 256>>>(src, dst, e);

    k_gemm1   <<<(n + 127) / 128, 256>>>(x, W1, n);
    k_agg1    <<<(n * 32 + 255) / 256, 256>>>(b1, n);
    k_gemm2   <<<(n + 127) / 128, 256>>>(W2, n);
    k_agg2out <<<(n * 32 + 255) / 256, 256>>>(b2, Wo, bo, (float*)d_out, n);
}

// round 7
// speedup vs baseline: 1.5161x; 1.0438x over previous
#include <cuda_runtime.h>
#include <cuda_fp16.h>

#define NN      100000
#define EE      1600000
#define INC     165
#define C1      128
#define C2      64

#define G1_BLOCKS   782              // ceil(NN/128) gemm1 tiles
#define HIST_BLOCKS 1600
#define NB_SCAN     49               // ceil(NN/2048)

// ---------------- scratch (static device globals; no runtime alloc) ----------------
__device__ int    g_cnt[NN];         // zero-initialized at load; re-zeroed by k_agg2out
__device__ int    g_cur[NN];
__device__ int    g_incl[NN];
__device__ int    g_rowptr[NN + 1];
__device__ int    g_bsum[128];
__device__ float  g_dinv[NN];
__device__ uint2  g_edge[EE];        // .x = src idx, .y = bits(dinv[src])
__device__ __half g_H1h[(size_t)NN * C1];
__device__ float  g_A1[(size_t)NN * C1];
__device__ __half g_H2h[(size_t)NN * C2];

// ---------------- tf32 helpers ----------------
__device__ __forceinline__ unsigned f2tf(float f) {
    unsigned u;
    asm("cvt.rna.tf32.f32 %0, %1;" : "=r"(u) : "f"(f));
    return u;
}

__device__ __forceinline__ void mma_tf32(float4& c,
                                         unsigned a0, unsigned a1, unsigned a2, unsigned a3,
                                         unsigned b0, unsigned b1) {
    asm volatile(
        "mma.sync.aligned.m16n8k8.row.col.f32.tf32.tf32.f32 "
        "{%0,%1,%2,%3}, {%4,%5,%6,%7}, {%8,%9}, {%0,%1,%2,%3};"
        : "+f"(c.x), "+f"(c.y), "+f"(c.z), "+f"(c.w)
        : "r"(a0), "r"(a1), "r"(a2), "r"(a3), "r"(b0), "r"(b1));
}

// ---------------- k_head: gemm1 tiles (blocks < G1_BLOCKS) + edge histogram ----------
__global__ __launch_bounds__(256) void k_head(const float* __restrict__ X,
                                              const float* __restrict__ W,
                                              const int* __restrict__ dst,
                                              int n, int e) {
    if (blockIdx.x >= G1_BLOCKS) {
        // ---- histogram branch (grid-stride) ----
        int i = (blockIdx.x - G1_BLOCKS) * 256 + threadIdx.x;
        for (; i < e; i += HIST_BLOCKS * 256)
            atomicAdd(&g_cnt[dst[i]], 1);
        return;
    }

    // ---- gemm1 tile: H1h = fp16(X @ W1), TF32, K-tile 32 ----
    __shared__ unsigned As[128 * 33];
    __shared__ unsigned Bs[32 * 136];

    int tid  = threadIdx.x;
    int wid  = tid >> 5;
    int lane = tid & 31;
    int g    = lane >> 2;
    int t    = lane & 3;
    int wm   = (wid & 3) * 32;
    int wn   = (wid >> 2) * 64;
    int rowBase = blockIdx.x * 128;

    float4 C[2][8];
#pragma unroll
    for (int a = 0; a < 2; a++)
#pragma unroll
        for (int b = 0; b < 8; b++) C[a][b] = make_float4(0.f, 0.f, 0.f, 0.f);

    for (int kt = 0; kt < 6; kt++) {        // 6*32 = 192 >= 165
        int k0 = kt * 32;
#pragma unroll
        for (int i = tid; i < 4096; i += 256) {
            int r = i >> 5, kk = i & 31;
            int gr = rowBase + r, gk = k0 + kk;
            float v = (gr < n && gk < INC) ? X[(size_t)gr * INC + gk] : 0.f;
            As[r * 33 + kk] = f2tf(v);
        }
#pragma unroll
        for (int i = tid; i < 4096; i += 256) {
            int kk = i >> 7, c = i & 127;
            int gk = k0 + kk;
            float v = (gk < INC) ? W[(size_t)gk * C1 + c] : 0.f;
            Bs[kk * 136 + c] = f2tf(v);
        }
        __syncthreads();

#pragma unroll
        for (int ks = 0; ks < 4; ks++) {
            int kb = ks * 8;
            unsigned a[2][4];
#pragma unroll
            for (int mg = 0; mg < 2; mg++) {
                int r = wm + mg * 16 + g;
                a[mg][0] = As[r * 33 + kb + t];
                a[mg][1] = As[(r + 8) * 33 + kb + t];
                a[mg][2] = As[r * 33 + kb + t + 4];
                a[mg][3] = As[(r + 8) * 33 + kb + t + 4];
            }
#pragma unroll
            for (int nc = 0; nc < 8; nc++) {
                int cb = wn + nc * 8 + g;
                unsigned b0 = Bs[(kb + t) * 136 + cb];
                unsigned b1 = Bs[(kb + t + 4) * 136 + cb];
                mma_tf32(C[0][nc], a[0][0], a[0][1], a[0][2], a[0][3], b0, b1);
                mma_tf32(C[1][nc], a[1][0], a[1][1], a[1][2], a[1][3], b0, b1);
            }
        }
        __syncthreads();
    }

#pragma unroll
    for (int mg = 0; mg < 2; mg++) {
        int r = rowBase + wm + mg * 16 + g;
#pragma unroll
        for (int nc = 0; nc < 8; nc++) {
            int c = wn + nc * 8 + 2 * t;
            if (r < n)
                *(__half2*)&g_H1h[(size_t)r * C1 + c] =
                    __floats2half2_rn(C[mg][nc].x, C[mg][nc].y);
            if (r + 8 < n)
                *(__half2*)&g_H1h[(size_t)(r + 8) * C1 + c] =
                    __floats2half2_rn(C[mg][nc].z, C[mg][nc].w);
        }
    }
}

// ---------------- scan1: per-block inclusive scan of g_cnt, block sums to g_bsum ----
__global__ void k_scan1(int n) {
    __shared__ int s[512];
    int tid  = threadIdx.x;
    int base = blockIdx.x * 2048 + tid * 4;
    int v[4];
    int local = 0;
#pragma unroll
    for (int i = 0; i < 4; i++) {
        int idx = base + i;
        int t = (idx < n) ? g_cnt[idx] : 0;
        v[i] = t; local += t;
    }
    s[tid] = local;
    __syncthreads();
    for (int off = 1; off < 512; off <<= 1) {
        int t = (tid >= off) ? s[tid - off] : 0;
        __syncthreads();
        s[tid] += t;
        __syncthreads();
    }
    int run = s[tid] - local;
#pragma unroll
    for (int i = 0; i < 4; i++) {
        run += v[i];
        int idx = base + i;
        if (idx < n) g_incl[idx] = run;
    }
    if (tid == 511) g_bsum[blockIdx.x] = s[511];
}

// ---------------- finalize: inline 49-entry block-offset scan + rowptr/dinv --------
__global__ void k_finalize(int n, int e) {
    __shared__ int bs[64];
    int tid = threadIdx.x;
    if (tid < 64) bs[tid] = (tid < NB_SCAN) ? g_bsum[tid] : 0;
    __syncthreads();
    if (tid == 0) {                     // tiny serial exclusive scan (49 adds)
        int run = 0;
#pragma unroll
        for (int i = 0; i < NB_SCAN; i++) {
            int t = bs[i]; bs[i] = run; run += t;
        }
    }
    __syncthreads();

    int i = blockIdx.x * blockDim.x + tid;
    if (i < n) {
        int rp = g_incl[i] - g_cnt[i] + bs[i >> 11];
        g_rowptr[i] = rp;
        g_cur[i]    = rp;
        g_dinv[i]   = rsqrtf((float)g_cnt[i] + 1.0f);
    }
    if (i == 0) g_rowptr[n] = e;
}

__global__ void k_fill(const int* __restrict__ src, const int* __restrict__ dst, int e) {
    int i = blockIdx.x * blockDim.x + threadIdx.x;
    if (i < e) {
        int s = src[i];
        int p = atomicAdd(&g_cur[dst[i]], 1);
        g_edge[p] = make_uint2((unsigned)s, __float_as_uint(g_dinv[s]));
    }
}

// ---------------- GEMM2: H2h = fp16(A1 @ W2)  (TF32, K-tile 32) ----------------
__global__ __launch_bounds__(256) void k_gemm2(const float* __restrict__ W, int n) {
    __shared__ unsigned As[128 * 33];
    __shared__ unsigned Bs[32 * 72];

    int tid  = threadIdx.x;
    int wid  = tid >> 5;
    int lane = tid & 31;
    int g    = lane >> 2;
    int t    = lane & 3;
    int wm   = wid * 16;
    int rowBase = blockIdx.x * 128;

    float4 C[8];
#pragma unroll
    for (int b = 0; b < 8; b++) C[b] = make_float4(0.f, 0.f, 0.f, 0.f);

    for (int kt = 0; kt < 4; kt++) {
        int k0 = kt * 32;
#pragma unroll
        for (int i = tid; i < 4096; i += 256) {
            int r = i >> 5, kk = i & 31;
            int gr = rowBase + r;
            float v = (gr < n) ? g_A1[(size_t)gr * C1 + k0 + kk] : 0.f;
            As[r * 33 + kk] = f2tf(v);
        }
#pragma unroll
        for (int i = tid; i < 2048; i += 256) {
            int kk = i >> 6, c = i & 63;
            Bs[kk * 72 + c] = f2tf(W[(size_t)(k0 + kk) * C2 + c]);
        }
        __syncthreads();

#pragma unroll
        for (int ks = 0; ks < 4; ks++) {
            int kb = ks * 8;
            int r = wm + g;
            unsigned a0 = As[r * 33 + kb + t];
            unsigned a1 = As[(r + 8) * 33 + kb + t];
            unsigned a2 = As[r * 33 + kb + t + 4];
            unsigned a3 = As[(r + 8) * 33 + kb + t + 4];
#pragma unroll
            for (int nc = 0; nc < 8; nc++) {
                int cb = nc * 8 + g;
                unsigned b0 = Bs[(kb + t) * 72 + cb];
                unsigned b1 = Bs[(kb + t + 4) * 72 + cb];
                mma_tf32(C[nc], a0, a1, a2, a3, b0, b1);
            }
        }
        __syncthreads();
    }

    int r = rowBase + wm + g;
#pragma unroll
    for (int nc = 0; nc < 8; nc++) {
        int c = nc * 8 + 2 * t;
        if (r < n)
            *(__half2*)&g_H2h[(size_t)r * C2 + c] = __floats2half2_rn(C[nc].x, C[nc].y);
        if (r + 8 < n)
            *(__half2*)&g_H2h[(size_t)(r + 8) * C2 + c] = __floats2half2_rn(C[nc].z, C[nc].w);
    }
}

// ---------------- agg1: warp per dst node, fp16 gathers (MLP=8), bias+relu ----------
__global__ void k_agg1(const float* __restrict__ b, int n) {
    int gidx = blockIdx.x * blockDim.x + threadIdx.x;
    int node = gidx >> 5;
    int lane = gidx & 31;
    if (node >= n) return;
    float di = g_dinv[node];

    uint2 v = *(const uint2*)(g_H1h + (size_t)node * C1 + 4 * lane);
    float2 p0 = __half22float2(*(__half2*)&v.x);
    float2 p1 = __half22float2(*(__half2*)&v.y);
    float a0 = di * p0.x, a1 = di * p0.y, a2 = di * p1.x, a3 = di * p1.y;

    int e   = g_rowptr[node];
    int end = g_rowptr[node + 1];
    for (; e + 7 < end; e += 8) {
        uint2 er[8], u[8];
#pragma unroll
        for (int j = 0; j < 8; j++) er[j] = g_edge[e + j];
#pragma unroll
        for (int j = 0; j < 8; j++)
            u[j] = *(const uint2*)(g_H1h + (size_t)er[j].x * C1 + 4 * lane);
#pragma unroll
        for (int j = 0; j < 8; j++) {
            float w = __uint_as_float(er[j].y);
            float2 q0 = __half22float2(*(__half2*)&u[j].x);
            float2 q1 = __half22float2(*(__half2*)&u[j].y);
            a0 += w * q0.x; a1 += w * q0.y;
            a2 += w * q1.x; a3 += w * q1.y;
        }
    }
    for (; e < end; e++) {
        uint2 e0 = g_edge[e];
        float w0 = __uint_as_float(e0.y);
        uint2 u0 = *(const uint2*)(g_H1h + (size_t)e0.x * C1 + 4 * lane);
        float2 q0 = __half22float2(*(__half2*)&u0.x);
        float2 q1 = __half22float2(*(__half2*)&u0.y);
        a0 += w0 * q0.x; a1 += w0 * q0.y;
        a2 += w0 * q1.x; a3 += w0 * q1.y;
    }
    float4 bb = *((const float4*)b + lane);
    float4 o;
    o.x = fmaxf(di * a0 + bb.x, 0.f);
    o.y = fmaxf(di * a1 + bb.y, 0.f);
    o.z = fmaxf(di * a2 + bb.z, 0.f);
    o.w = fmaxf(di * a3 + bb.w, 0.f);
    *((float4*)(g_A1 + (size_t)node * C1) + lane) = o;
}

// ---------------- agg2 (fp16 gathers, MLP=8) + output projection + cnt re-zero -----
__global__ void k_agg2out(const float* __restrict__ b, const float* __restrict__ Wo,
                          const float* __restrict__ bo, float* __restrict__ out, int n) {
    int gidx = blockIdx.x * blockDim.x + threadIdx.x;
    int node = gidx >> 5;
    int lane = gidx & 31;
    if (node >= n) return;
    float di = g_dinv[node];

    float2 p = __half22float2(*(const __half2*)(g_H2h + (size_t)node * C2 + 2 * lane));
    float a0 = di * p.x, a1 = di * p.y;

    int e   = g_rowptr[node];
    int end = g_rowptr[node + 1];
    for (; e + 7 < end; e += 8) {
        uint2 er[8];
        __half2 h[8];
#pragma unroll
        for (int j = 0; j < 8; j++) er[j] = g_edge[e + j];
#pragma unroll
        for (int j = 0; j < 8; j++)
            h[j] = *(const __half2*)(g_H2h + (size_t)er[j].x * C2 + 2 * lane);
#pragma unroll
        for (int j = 0; j < 8; j++) {
            float w = __uint_as_float(er[j].y);
            float2 q = __half22float2(h[j]);
            a0 += w * q.x; a1 += w * q.y;
        }
    }
    for (; e < end; e++) {
        uint2 e0 = g_edge[e];
        float w0 = __uint_as_float(e0.y);
        float2 q = __half22float2(*(const __half2*)(g_H2h + (size_t)e0.x * C2 + 2 * lane));
        a0 += w0 * q.x; a1 += w0 * q.y;
    }
    float2 bb = *((const float2*)b + lane);
    float ox = fmaxf(di * a0 + bb.x, 0.f);
    float oy = fmaxf(di * a1 + bb.y, 0.f);

    int ch = 2 * lane;
    float d0 = ox * Wo[ch * 2]     + oy * Wo[(ch + 1) * 2];
    float d1 = ox * Wo[ch * 2 + 1] + oy * Wo[(ch + 1) * 2 + 1];
#pragma unroll
    for (int m = 16; m > 0; m >>= 1) {
        d0 += __shfl_xor_sync(0xFFFFFFFFu, d0, m);
        d1 += __shfl_xor_sync(0xFFFFFFFFu, d1, m);
    }
    if (lane == 0) {
        float2 r;
        r.x = d0 + bo[0];
        r.y = d1 + bo[1];
        ((float2*)out)[node] = r;
        g_cnt[node] = 0;            // re-zero histogram for the next graph replay
    }
}

// ---------------- launch ----------------
extern "C" void kernel_launch(void* const* d_in, const int* in_sizes, int n_in,
                              void* d_out, int out_size) {
    const float* x   = (const float*)d_in[0];
    const int*   ei  = (const int*)  d_in[1];
    const float* W1  = (const float*)d_in[2];
    const float* b1  = (const float*)d_in[3];
    const float* W2  = (const float*)d_in[4];
    const float* b2  = (const float*)d_in[5];
    const float* Wo  = (const float*)d_in[6];
    const float* bo  = (const float*)d_in[7];

    int n = in_sizes[0] / INC;
    int e = in_sizes[1] / 2;
    const int* src = ei;
    const int* dst = ei + e;

    k_head    <<<G1_BLOCKS + HIST_BLOCKS, 256>>>(x, W1, dst, n, e);
    k_scan1   <<<NB_SCAN, 512>>>(n);
    k_finalize<<<(n + 255) / 256, 256>>>(n, e);
    k_fill    <<<(e + 255) / 256, 256>>>(src, dst, e);
    k_agg1    <<<(n * 32 + 255) / 256, 256>>>(b1, n);
    k_gemm2   <<<(n + 127) / 128, 256>>>(W2, n);
    k_agg2out <<<(n * 32 + 255) / 256, 256>>>(b2, Wo, bo, (float*)d_out, n);
}